// round 1
// baseline (speedup 1.0000x reference)
#include <cuda_runtime.h>

#define NN 50000
#define EE 800000
#define DIM 128
#define NEG_SLOPE 0.2f

// ---------------- scratch (no allocs allowed) ----------------
__device__ __align__(16) float g_h[NN * DIM];
__device__ __align__(16) float g_bufA[NN * DIM];
__device__ __align__(16) float g_bufB[NN * DIM];
__device__ float g_al[NN];
__device__ float g_ar[NN];
__device__ __align__(16) float g_was[DIM];
__device__ __align__(16) float g_wad[DIM];
__device__ int g_rpA[NN + 1];
__device__ int g_rpB[NN + 1];
__device__ int g_colA[EE];
__device__ int g_colB[EE];
__device__ int g_deg[NN];
__device__ int g_cnt[NN];

__device__ __forceinline__ float lrelu(float v) { return v > 0.f ? v : NEG_SLOPE * v; }

// packed f32x2 helpers (FFMA2: 2x fp32 FMA throughput on sm_103a)
__device__ __forceinline__ void fma2(unsigned long long& d, unsigned long long a, unsigned long long b) {
    asm("fma.rn.f32x2 %0, %1, %2, %0;" : "+l"(d) : "l"(a), "l"(b));
}
__device__ __forceinline__ unsigned long long pk2(float a, float b) {
    unsigned long long r; asm("mov.b64 %0, {%1, %2};" : "=l"(r) : "f"(a), "f"(b)); return r;
}
__device__ __forceinline__ float2 up2(unsigned long long u) {
    float2 r; asm("mov.b64 {%0, %1}, %2;" : "=f"(r.x), "=f"(r.y) : "l"(u)); return r;
}

// ---------------- CSR build ----------------
__global__ void zero_int_kernel(int* p, int n) {
    int i = blockIdx.x * blockDim.x + threadIdx.x;
    if (i < n) p[i] = 0;
}
__global__ void hist_kernel(const int* __restrict__ dst, int* deg, int E) {
    int i = blockIdx.x * blockDim.x + threadIdx.x;
    if (i < E) atomicAdd(&deg[dst[i]], 1);
}
__global__ void copy_int_kernel(int* d, const int* __restrict__ s, int n) {
    int i = blockIdx.x * blockDim.x + threadIdx.x;
    if (i < n) d[i] = s[i];
}
__global__ void scatter_kernel(const int* __restrict__ src, const int* __restrict__ dst,
                               int* cnt, int* col, int E) {
    int i = blockIdx.x * blockDim.x + threadIdx.x;
    if (i < E) {
        int p = atomicAdd(&cnt[dst[i]], 1);
        col[p] = src[i];
    }
}
// single-block exclusive scan: rowptr[0]=0, rowptr[i+1]=sum(deg[0..i])
__global__ void scan_kernel(const int* __restrict__ deg, int* __restrict__ rowptr, int n) {
    __shared__ int sh[1024];
    int tid = threadIdx.x;
    int carry = 0;
    for (int base = 0; base < n; base += 1024) {
        int i = base + tid;
        int v = (i < n) ? deg[i] : 0;
        sh[tid] = v;
        __syncthreads();
        for (int off = 1; off < 1024; off <<= 1) {
            int t = (tid >= off) ? sh[tid - off] : 0;
            __syncthreads();
            sh[tid] += t;
            __syncthreads();
        }
        if (i < n) rowptr[i + 1] = carry + sh[tid];
        carry += sh[1023];
        __syncthreads();
    }
    if (tid == 0) rowptr[0] = 0;
}

// ---------------- wa = W @ a  (al = x @ wa trick) ----------------
__global__ void wa_kernel(const float* __restrict__ W, const float* __restrict__ a_s,
                          const float* __restrict__ a_d, float* __restrict__ was,
                          float* __restrict__ wad) {
    int k = threadIdx.x;  // 128 threads
    const float* wr = W + k * DIM;
    float s = 0.f, d = 0.f;
#pragma unroll 4
    for (int c = 0; c < DIM; c++) {
        float wv = wr[c];
        s += wv * a_s[c];
        d += wv * a_d[c];
    }
    was[k] = s;
    wad[k] = d;
}

// ---------------- al/ar: warp per node ----------------
__global__ void __launch_bounds__(256) alr_kernel(const float* __restrict__ X,
                                                  const float* __restrict__ was,
                                                  const float* __restrict__ wad,
                                                  float* __restrict__ al, float* __restrict__ ar,
                                                  int n) {
    int w = (blockIdx.x * blockDim.x + threadIdx.x) >> 5;
    int lane = threadIdx.x & 31;
    if (w >= n) return;
    float4 xv = ((const float4*)X)[(size_t)w * 32 + lane];
    float4 s4 = ((const float4*)was)[lane];
    float4 d4 = ((const float4*)wad)[lane];
    float a = xv.x * s4.x + xv.y * s4.y + xv.z * s4.z + xv.w * s4.w;
    float b = xv.x * d4.x + xv.y * d4.y + xv.z * d4.z + xv.w * d4.w;
#pragma unroll
    for (int o = 16; o; o >>= 1) {
        a += __shfl_xor_sync(0xffffffffu, a, o);
        b += __shfl_xor_sync(0xffffffffu, b, o);
    }
    if (lane == 0) { al[w] = a; ar[w] = b; }
}

// ---------------- GEMM: 128x128 tile, 8x8/thread, f32x2 FMA ----------------
__global__ void __launch_bounds__(256) gemm_kernel(const float* __restrict__ X,
                                                   const float* __restrict__ W,
                                                   float* __restrict__ H, int nrows) {
    __shared__ float xs[128][33];
    __shared__ __align__(16) float ws[32][128];
    int row0 = blockIdx.x * 128;
    int t = threadIdx.x;
    int tx = t & 15, ty = t >> 4;

    unsigned long long acc[8][4];
#pragma unroll
    for (int r = 0; r < 8; r++)
#pragma unroll
        for (int p = 0; p < 4; p++) acc[r][p] = 0ULL;

#pragma unroll 1
    for (int k0 = 0; k0 < DIM; k0 += 32) {
#pragma unroll
        for (int i = 0; i < 4; i++) {
            int slot = t + i * 256;          // 1024 float4 slots = 128 rows x 8
            int r = slot >> 3;
            int k4 = (slot & 7) << 2;
            float4 v = make_float4(0.f, 0.f, 0.f, 0.f);
            if (row0 + r < nrows) v = *(const float4*)(X + (size_t)(row0 + r) * DIM + k0 + k4);
            xs[r][k4 + 0] = v.x; xs[r][k4 + 1] = v.y; xs[r][k4 + 2] = v.z; xs[r][k4 + 3] = v.w;
        }
#pragma unroll
        for (int i = 0; i < 4; i++) {
            int slot = t + i * 256;          // 1024 float4 slots = 32 k x 32
            int kk = slot >> 5;
            int c4 = (slot & 31) << 2;
            *(float4*)(&ws[kk][c4]) = *(const float4*)(W + (size_t)(k0 + kk) * DIM + c4);
        }
        __syncthreads();
#pragma unroll
        for (int kk = 0; kk < 32; kk++) {
            ulonglong2 wA = *(const ulonglong2*)(&ws[kk][tx * 8]);      // cols c0..c3 as 2 pairs
            ulonglong2 wB = *(const ulonglong2*)(&ws[kk][tx * 8 + 4]);  // cols c4..c7
#pragma unroll
            for (int r = 0; r < 8; r++) {
                float xv = xs[ty * 8 + r][kk];
                unsigned long long xd = pk2(xv, xv);
                fma2(acc[r][0], xd, wA.x);
                fma2(acc[r][1], xd, wA.y);
                fma2(acc[r][2], xd, wB.x);
                fma2(acc[r][3], xd, wB.y);
            }
        }
        __syncthreads();
    }
#pragma unroll
    for (int r = 0; r < 8; r++) {
        int row = row0 + ty * 8 + r;
        if (row < nrows) {
            float2 p0 = up2(acc[r][0]), p1 = up2(acc[r][1]);
            float2 p2 = up2(acc[r][2]), p3 = up2(acc[r][3]);
            ((float4*)H)[(size_t)row * 32 + tx * 2 + 0] = make_float4(p0.x, p0.y, p1.x, p1.y);
            ((float4*)H)[(size_t)row * 32 + tx * 2 + 1] = make_float4(p2.x, p2.y, p3.x, p3.y);
        }
    }
}

// ---------------- GAT aggregation: warp per dst node ----------------
__global__ void __launch_bounds__(256) aggregate_kernel(
    const float* __restrict__ H, const float* __restrict__ al, const float* __restrict__ ar,
    const int* __restrict__ rowptr, const int* __restrict__ col,
    const float* __restrict__ bias, float* __restrict__ out, int n, int do_relu) {
    int w = (blockIdx.x * blockDim.x + threadIdx.x) >> 5;
    int lane = threadIdx.x & 31;
    if (w >= n) return;
    int start = rowptr[w];
    int end = rowptr[w + 1];
    float ard = ar[w];
    float e_self = lrelu(al[w] + ard);

    // phase 1: segment max (self-loop included)
    float m = e_self;
    for (int j = start + lane; j < end; j += 32) {
        m = fmaxf(m, lrelu(al[col[j]] + ard));
    }
#pragma unroll
    for (int o = 16; o; o >>= 1) m = fmaxf(m, __shfl_xor_sync(0xffffffffu, m, o));

    // phase 2: weighted accumulation (unnormalized) + weight sum
    const float4* H4 = (const float4*)H;
    float w_self = __expf(e_self - m);
    float4 hv = H4[(size_t)w * 32 + lane];
    float4 acc;
    acc.x = w_self * hv.x; acc.y = w_self * hv.y; acc.z = w_self * hv.z; acc.w = w_self * hv.w;
    float ssum = w_self;

    for (int base = start; base < end; base += 32) {
        int j = base + lane;
        int sj = 0;
        float wj = 0.f;
        if (j < end) {
            sj = col[j];
            wj = __expf(lrelu(al[sj] + ard) - m);
        }
        int cnt = min(32, end - base);
        for (int tt = 0; tt < cnt; tt++) {
            int s = __shfl_sync(0xffffffffu, sj, tt);
            float wt = __shfl_sync(0xffffffffu, wj, tt);
            float4 h2 = H4[(size_t)s * 32 + lane];
            acc.x += wt * h2.x; acc.y += wt * h2.y;
            acc.z += wt * h2.z; acc.w += wt * h2.w;
            ssum += wt;
        }
    }
    float inv = 1.0f / ssum;
    float4 bv = ((const float4*)bias)[lane];
    float4 o;
    o.x = acc.x * inv + bv.x; o.y = acc.y * inv + bv.y;
    o.z = acc.z * inv + bv.z; o.w = acc.w * inv + bv.w;
    if (do_relu) {
        o.x = fmaxf(o.x, 0.f); o.y = fmaxf(o.y, 0.f);
        o.z = fmaxf(o.z, 0.f); o.w = fmaxf(o.w, 0.f);
    }
    ((float4*)out)[(size_t)w * 32 + lane] = o;
}

// ---------------- launch ----------------
extern "C" void kernel_launch(void* const* d_in, const int* in_sizes, int n_in,
                              void* d_out, int out_size) {
    const float* x = (const float*)d_in[0];
    const float* W[5]; const float* As[5]; const float* Ad[5]; const float* B[5];
    for (int i = 0; i < 5; i++) {
        W[i]  = (const float*)d_in[1 + 4 * i];
        As[i] = (const float*)d_in[2 + 4 * i];
        Ad[i] = (const float*)d_in[3 + 4 * i];
        B[i]  = (const float*)d_in[4 + 4 * i];
    }
    const int* ei  = (const int*)d_in[21];
    const int* eic = (const int*)d_in[22];
    float* out = (float*)d_out;

    float *h, *bufA, *bufB, *al, *ar, *was, *wad;
    int *rpA, *rpB, *colA, *colB, *deg, *cnt;
    cudaGetSymbolAddress((void**)&h, g_h);
    cudaGetSymbolAddress((void**)&bufA, g_bufA);
    cudaGetSymbolAddress((void**)&bufB, g_bufB);
    cudaGetSymbolAddress((void**)&al, g_al);
    cudaGetSymbolAddress((void**)&ar, g_ar);
    cudaGetSymbolAddress((void**)&was, g_was);
    cudaGetSymbolAddress((void**)&wad, g_wad);
    cudaGetSymbolAddress((void**)&rpA, g_rpA);
    cudaGetSymbolAddress((void**)&rpB, g_rpB);
    cudaGetSymbolAddress((void**)&colA, g_colA);
    cudaGetSymbolAddress((void**)&colB, g_colB);
    cudaGetSymbolAddress((void**)&deg, g_deg);
    cudaGetSymbolAddress((void**)&cnt, g_cnt);

    const int N = NN, E = EE;
    int Gz = (N + 255) / 256;
    int Ge = (E + 255) / 256;
    int Gagg = (N * 32 + 255) / 256;
    int Gg = (N + 127) / 128;

    // CSR for edge_index (layers 1,3,5)
    zero_int_kernel<<<Gz, 256>>>(deg, N);
    hist_kernel<<<Ge, 256>>>(ei + E, deg, E);
    scan_kernel<<<1, 1024>>>(deg, rpA, N);
    copy_int_kernel<<<Gz, 256>>>(cnt, rpA, N);
    scatter_kernel<<<Ge, 256>>>(ei, ei + E, cnt, colA, E);

    // CSR for edge_index_cross (layers 2,4)
    zero_int_kernel<<<Gz, 256>>>(deg, N);
    hist_kernel<<<Ge, 256>>>(eic + E, deg, E);
    scan_kernel<<<1, 1024>>>(deg, rpB, N);
    copy_int_kernel<<<Gz, 256>>>(cnt, rpB, N);
    scatter_kernel<<<Ge, 256>>>(eic, eic + E, cnt, colB, E);

    const float* xin[5] = { x, bufA, bufB, bufA, bufB };
    float* xout[5]      = { bufA, bufB, bufA, bufB, out };
    const int* rp[5]    = { rpA, rpB, rpA, rpB, rpA };
    const int* cl[5]    = { colA, colB, colA, colB, colA };

    for (int i = 0; i < 5; i++) {
        wa_kernel<<<1, 128>>>(W[i], As[i], Ad[i], was, wad);
        gemm_kernel<<<Gg, 256>>>(xin[i], W[i], h, N);
        alr_kernel<<<Gagg, 256>>>(xin[i], was, wad, al, ar, N);
        aggregate_kernel<<<Gagg, 256>>>(h, al, ar, rp[i], cl[i], B[i], xout[i], N,
                                        i < 4 ? 1 : 0);
    }
}

// round 2
// speedup vs baseline: 1.4983x; 1.4983x over previous
#include <cuda_runtime.h>

#define NN 50000
#define EE 800000
#define DIM 128
#define NEG_SLOPE 0.2f

typedef unsigned long long ull;

// ---------------- scratch (no allocs allowed) ----------------
__device__ __align__(16) float g_h[NN * DIM];
__device__ __align__(16) float g_bufA[NN * DIM];
__device__ __align__(16) float g_bufB[NN * DIM];
__device__ float g_al[NN];
__device__ float g_ar[NN];
__device__ int g_rpA[NN + 1];
__device__ int g_rpB[NN + 1];
__device__ int g_colA[EE];
__device__ int g_colB[EE];
__device__ int g_degA[NN];
__device__ int g_degB[NN];
__device__ int g_cntA[NN];
__device__ int g_cntB[NN];

__device__ __forceinline__ float lrelu(float v) { return v > 0.f ? v : NEG_SLOPE * v; }

// packed f32x2 helpers (FFMA2: 2x fp32 FMA throughput on sm_103a)
__device__ __forceinline__ void fma2(ull& d, ull a, ull b) {
    asm("fma.rn.f32x2 %0, %1, %2, %0;" : "+l"(d) : "l"(a), "l"(b));
}
__device__ __forceinline__ ull pk2(float a, float b) {
    ull r; asm("mov.b64 %0, {%1, %2};" : "=l"(r) : "f"(a), "f"(b)); return r;
}
__device__ __forceinline__ float2 up2(ull u) {
    float2 r; asm("mov.b64 {%0, %1}, %2;" : "=f"(r.x), "=f"(r.y) : "l"(u)); return r;
}

// ---------------- CSR build (A and B fused) ----------------
__global__ void zero2_kernel(int* degA, int* degB, int n) {
    int i = blockIdx.x * blockDim.x + threadIdx.x;
    if (i < n) degA[i] = 0;
    else if (i < 2 * n) degB[i - n] = 0;
}
__global__ void hist2_kernel(const int* __restrict__ dstA, const int* __restrict__ dstB,
                             int* degA, int* degB, int E) {
    int i = blockIdx.x * blockDim.x + threadIdx.x;
    if (i < E) atomicAdd(&degA[dstA[i]], 1);
    else if (i < 2 * E) atomicAdd(&degB[dstB[i - E]], 1);
}
// 2 blocks: block 0 scans degA -> rpA/cntA, block 1 scans degB -> rpB/cntB.
// shfl-based scan, 4 elems/thread, also writes the cnt (= exclusive prefix) copy.
__global__ void scan2_kernel(const int* __restrict__ degA, const int* __restrict__ degB,
                             int* rpA, int* rpB, int* cntA, int* cntB, int n) {
    const int* deg = (blockIdx.x == 0) ? degA : degB;
    int* rp  = (blockIdx.x == 0) ? rpA : rpB;
    int* cnt = (blockIdx.x == 0) ? cntA : cntB;
    __shared__ int wsum[32];
    int tid = threadIdx.x, lane = tid & 31, wid = tid >> 5;
    int carry = 0;
    if (tid == 0) rp[0] = 0;
    for (int base = 0; base < n; base += 4096) {
        int i0 = base + tid * 4;
        int v[4];
#pragma unroll
        for (int k = 0; k < 4; k++) v[k] = (i0 + k < n) ? deg[i0 + k] : 0;
        int tsum = v[0] + v[1] + v[2] + v[3];
        int inc = tsum;
#pragma unroll
        for (int o = 1; o < 32; o <<= 1) {
            int t = __shfl_up_sync(0xffffffffu, inc, o);
            if (lane >= o) inc += t;
        }
        if (lane == 31) wsum[wid] = inc;
        __syncthreads();
        if (wid == 0) {
            int w = wsum[lane];
#pragma unroll
            for (int o = 1; o < 32; o <<= 1) {
                int t = __shfl_up_sync(0xffffffffu, w, o);
                if (lane >= o) w += t;
            }
            wsum[lane] = w;
        }
        __syncthreads();
        int woff = wid ? wsum[wid - 1] : 0;
        int excl = carry + woff + inc - tsum;
#pragma unroll
        for (int k = 0; k < 4; k++) {
            if (i0 + k < n) {
                cnt[i0 + k] = excl;
                excl += v[k];
                rp[i0 + k + 1] = excl;
            }
        }
        carry += wsum[31];
        __syncthreads();
    }
}
__global__ void scatter2_kernel(const int* __restrict__ eiA, const int* __restrict__ eiB,
                                int* cntA, int* cntB, int* colA, int* colB, int E) {
    int i = blockIdx.x * blockDim.x + threadIdx.x;
    if (i < E) {
        int p = atomicAdd(&cntA[eiA[E + i]], 1);
        colA[p] = eiA[i];
    } else if (i < 2 * E) {
        int j = i - E;
        int p = atomicAdd(&cntB[eiB[E + j]], 1);
        colB[p] = eiB[j];
    }
}

// ---------------- GEMM (128x128 tile, 8x8/thread, f32x2) + fused al/ar ----------------
__global__ void __launch_bounds__(256, 2) gemm_fused_kernel(
    const float* __restrict__ X, const float* __restrict__ W,
    const float* __restrict__ a_s, const float* __restrict__ a_d,
    float* __restrict__ H, float* __restrict__ al, float* __restrict__ ar, int nrows) {
    __shared__ float xs[32][132];                 // [k][row], pad keeps 16B align + low conflict
    __shared__ __align__(16) float ws[32][128];   // [k][col]
    int row0 = blockIdx.x * 128;
    int t = threadIdx.x;
    int tx = t & 15, ty = t >> 4;

    ull acc[8][4];
#pragma unroll
    for (int r = 0; r < 8; r++)
#pragma unroll
        for (int p = 0; p < 4; p++) acc[r][p] = 0ULL;

#pragma unroll 1
    for (int k0 = 0; k0 < DIM; k0 += 32) {
#pragma unroll
        for (int i = 0; i < 4; i++) {
            int slot = t + i * 256;          // 1024 float4 slots = 128 rows x 8 k-quads
            int r = slot >> 3;
            int kq = (slot & 7) << 2;
            float4 v = make_float4(0.f, 0.f, 0.f, 0.f);
            if (row0 + r < nrows) v = *(const float4*)(X + (size_t)(row0 + r) * DIM + k0 + kq);
            xs[kq + 0][r] = v.x; xs[kq + 1][r] = v.y; xs[kq + 2][r] = v.z; xs[kq + 3][r] = v.w;
        }
#pragma unroll
        for (int i = 0; i < 4; i++) {
            int slot = t + i * 256;          // 1024 float4 slots = 32 k x 32 col-quads
            int kk = slot >> 5;
            int c4 = (slot & 31) << 2;
            *(float4*)(&ws[kk][c4]) = *(const float4*)(W + (size_t)(k0 + kk) * DIM + c4);
        }
        __syncthreads();
#pragma unroll
        for (int kk = 0; kk < 32; kk++) {
            float4 xa = *(const float4*)(&xs[kk][ty * 8]);       // broadcast within warp halves
            float4 xb = *(const float4*)(&xs[kk][ty * 8 + 4]);
            ulonglong2 wA = *(const ulonglong2*)(&ws[kk][tx * 8]);
            ulonglong2 wB = *(const ulonglong2*)(&ws[kk][tx * 8 + 4]);
            ull xd;
            xd = pk2(xa.x, xa.x);
            fma2(acc[0][0], xd, wA.x); fma2(acc[0][1], xd, wA.y);
            fma2(acc[0][2], xd, wB.x); fma2(acc[0][3], xd, wB.y);
            xd = pk2(xa.y, xa.y);
            fma2(acc[1][0], xd, wA.x); fma2(acc[1][1], xd, wA.y);
            fma2(acc[1][2], xd, wB.x); fma2(acc[1][3], xd, wB.y);
            xd = pk2(xa.z, xa.z);
            fma2(acc[2][0], xd, wA.x); fma2(acc[2][1], xd, wA.y);
            fma2(acc[2][2], xd, wB.x); fma2(acc[2][3], xd, wB.y);
            xd = pk2(xa.w, xa.w);
            fma2(acc[3][0], xd, wA.x); fma2(acc[3][1], xd, wA.y);
            fma2(acc[3][2], xd, wB.x); fma2(acc[3][3], xd, wB.y);
            xd = pk2(xb.x, xb.x);
            fma2(acc[4][0], xd, wA.x); fma2(acc[4][1], xd, wA.y);
            fma2(acc[4][2], xd, wB.x); fma2(acc[4][3], xd, wB.y);
            xd = pk2(xb.y, xb.y);
            fma2(acc[5][0], xd, wA.x); fma2(acc[5][1], xd, wA.y);
            fma2(acc[5][2], xd, wB.x); fma2(acc[5][3], xd, wB.y);
            xd = pk2(xb.z, xb.z);
            fma2(acc[6][0], xd, wA.x); fma2(acc[6][1], xd, wA.y);
            fma2(acc[6][2], xd, wB.x); fma2(acc[6][3], xd, wB.y);
            xd = pk2(xb.w, xb.w);
            fma2(acc[7][0], xd, wA.x); fma2(acc[7][1], xd, wA.y);
            fma2(acc[7][2], xd, wB.x); fma2(acc[7][3], xd, wB.y);
        }
        __syncthreads();
    }

    // epilogue: store H and compute al = h@a_src, ar = h@a_dst
    float as8[8], ad8[8];
#pragma unroll
    for (int c = 0; c < 8; c++) {
        as8[c] = __ldg(a_s + tx * 8 + c);
        ad8[c] = __ldg(a_d + tx * 8 + c);
    }
#pragma unroll
    for (int r = 0; r < 8; r++) {
        int row = row0 + ty * 8 + r;
        float2 p0 = up2(acc[r][0]), p1 = up2(acc[r][1]);
        float2 p2 = up2(acc[r][2]), p3 = up2(acc[r][3]);
        if (row < nrows) {
            ((float4*)H)[(size_t)row * 32 + tx * 2 + 0] = make_float4(p0.x, p0.y, p1.x, p1.y);
            ((float4*)H)[(size_t)row * 32 + tx * 2 + 1] = make_float4(p2.x, p2.y, p3.x, p3.y);
        }
        float hv[8] = { p0.x, p0.y, p1.x, p1.y, p2.x, p2.y, p3.x, p3.y };
        float pal = 0.f, par = 0.f;
#pragma unroll
        for (int c = 0; c < 8; c++) {
            pal += hv[c] * as8[c];
            par += hv[c] * ad8[c];
        }
#pragma unroll
        for (int o = 8; o; o >>= 1) {
            pal += __shfl_xor_sync(0xffffffffu, pal, o);
            par += __shfl_xor_sync(0xffffffffu, par, o);
        }
        if (tx == 0 && row < nrows) {
            al[row] = pal;
            ar[row] = par;
        }
    }
}

// ---------------- GAT aggregation: warp per dst node, online softmax ----------------
__global__ void __launch_bounds__(256) aggregate_kernel(
    const float* __restrict__ H, const float* __restrict__ al, const float* __restrict__ ar,
    const int* __restrict__ rowptr, const int* __restrict__ col,
    const float* __restrict__ bias, float* __restrict__ out, int n, int do_relu) {
    int w = (blockIdx.x * blockDim.x + threadIdx.x) >> 5;
    int lane = threadIdx.x & 31;
    if (w >= n) return;
    int start = rowptr[w];
    int end = rowptr[w + 1];
    float ard = ar[w];
    float m = lrelu(al[w] + ard);          // self-loop energy; running max

    const float4* H4 = (const float4*)H;
    float4 acc = H4[(size_t)w * 32 + lane];  // self-loop contribution, weight exp(0)=1
    float ssum = (lane == 0) ? 1.f : 0.f;    // per-lane partial sums of weights

    for (int base = start; base < end; base += 32) {
        int j = base + lane;
        int sj = 0;
        float ej = -1e30f;
        if (j < end) {
            sj = __ldg(&col[j]);
            ej = lrelu(__ldg(&al[sj]) + ard);
        }
        // batch max
        float bm = ej;
#pragma unroll
        for (int o = 16; o; o >>= 1) bm = fmaxf(bm, __shfl_xor_sync(0xffffffffu, bm, o));
        if (bm > m) {
            float sc = __expf(m - bm);
            m = bm;
            acc.x *= sc; acc.y *= sc; acc.z *= sc; acc.w *= sc;
            ssum *= sc;
        }
        float wj = (j < end) ? __expf(ej - m) : 0.f;
        ssum += wj;
        int cnt = min(32, end - base);
#pragma unroll 4
        for (int tt = 0; tt < cnt; tt++) {
            int s = __shfl_sync(0xffffffffu, sj, tt);
            float wt = __shfl_sync(0xffffffffu, wj, tt);
            float4 h2 = H4[(size_t)s * 32 + lane];
            acc.x += wt * h2.x; acc.y += wt * h2.y;
            acc.z += wt * h2.z; acc.w += wt * h2.w;
        }
    }
    // total weight
#pragma unroll
    for (int o = 16; o; o >>= 1) ssum += __shfl_xor_sync(0xffffffffu, ssum, o);
    float inv = 1.0f / ssum;
    float4 bv = ((const float4*)bias)[lane];
    float4 o;
    o.x = acc.x * inv + bv.x; o.y = acc.y * inv + bv.y;
    o.z = acc.z * inv + bv.z; o.w = acc.w * inv + bv.w;
    if (do_relu) {
        o.x = fmaxf(o.x, 0.f); o.y = fmaxf(o.y, 0.f);
        o.z = fmaxf(o.z, 0.f); o.w = fmaxf(o.w, 0.f);
    }
    ((float4*)out)[(size_t)w * 32 + lane] = o;
}

// ---------------- launch ----------------
extern "C" void kernel_launch(void* const* d_in, const int* in_sizes, int n_in,
                              void* d_out, int out_size) {
    const float* x = (const float*)d_in[0];
    const float* W[5]; const float* As[5]; const float* Ad[5]; const float* B[5];
    for (int i = 0; i < 5; i++) {
        W[i]  = (const float*)d_in[1 + 4 * i];
        As[i] = (const float*)d_in[2 + 4 * i];
        Ad[i] = (const float*)d_in[3 + 4 * i];
        B[i]  = (const float*)d_in[4 + 4 * i];
    }
    const int* ei  = (const int*)d_in[21];
    const int* eic = (const int*)d_in[22];
    float* out = (float*)d_out;

    float *h, *bufA, *bufB, *al, *ar;
    int *rpA, *rpB, *colA, *colB, *degA, *degB, *cntA, *cntB;
    cudaGetSymbolAddress((void**)&h, g_h);
    cudaGetSymbolAddress((void**)&bufA, g_bufA);
    cudaGetSymbolAddress((void**)&bufB, g_bufB);
    cudaGetSymbolAddress((void**)&al, g_al);
    cudaGetSymbolAddress((void**)&ar, g_ar);
    cudaGetSymbolAddress((void**)&rpA, g_rpA);
    cudaGetSymbolAddress((void**)&rpB, g_rpB);
    cudaGetSymbolAddress((void**)&colA, g_colA);
    cudaGetSymbolAddress((void**)&colB, g_colB);
    cudaGetSymbolAddress((void**)&degA, g_degA);
    cudaGetSymbolAddress((void**)&degB, g_degB);
    cudaGetSymbolAddress((void**)&cntA, g_cntA);
    cudaGetSymbolAddress((void**)&cntB, g_cntB);

    const int N = NN, E = EE;
    int Gz2 = (2 * N + 255) / 256;
    int Ge2 = (2 * E + 255) / 256;
    int Gagg = (N * 32 + 255) / 256;
    int Gg = (N + 127) / 128;

    // CSR build: 4 launches total
    zero2_kernel<<<Gz2, 256>>>(degA, degB, N);
    hist2_kernel<<<Ge2, 256>>>(ei + E, eic + E, degA, degB, E);
    scan2_kernel<<<2, 1024>>>(degA, degB, rpA, rpB, cntA, cntB, N);
    scatter2_kernel<<<Ge2, 256>>>(ei, eic, cntA, cntB, colA, colB, E);

    const float* xin[5] = { x, bufA, bufB, bufA, bufB };
    float* xout[5]      = { bufA, bufB, bufA, bufB, out };
    const int* rp[5]    = { rpA, rpB, rpA, rpB, rpA };
    const int* cl[5]    = { colA, colB, colA, colB, colA };

    for (int i = 0; i < 5; i++) {
        gemm_fused_kernel<<<Gg, 256>>>(xin[i], W[i], As[i], Ad[i], h, al, ar, N);
        aggregate_kernel<<<Gagg, 256>>>(h, al, ar, rp[i], cl[i], B[i], xout[i], N,
                                        i < 4 ? 1 : 0);
    }
}

// round 3
// speedup vs baseline: 1.5683x; 1.0467x over previous
#include <cuda_runtime.h>
#include <cuda_fp16.h>

#define NN 50000
#define EE 800000
#define DIM 128
#define NEG_SLOPE 0.2f

typedef unsigned long long ull;

// ---------------- scratch (no allocs allowed) ----------------
__device__ __align__(16) __half g_h[NN * DIM];     // fp16 H (gather payload)
__device__ __align__(16) float g_bufA[NN * DIM];
__device__ __align__(16) float g_bufB[NN * DIM];
__device__ float g_al[NN];
__device__ float g_ar[NN];
__device__ int g_rpA[NN + 1];
__device__ int g_rpB[NN + 1];
__device__ int g_colA[EE];
__device__ int g_colB[EE];
__device__ int g_degA[NN];
__device__ int g_degB[NN];
__device__ int g_cntA[NN];
__device__ int g_cntB[NN];

__device__ __forceinline__ float lrelu(float v) { return v > 0.f ? v : NEG_SLOPE * v; }

// packed f32x2 helpers (FFMA2: 2x fp32 FMA throughput on sm_103a)
__device__ __forceinline__ void fma2(ull& d, ull a, ull b) {
    asm("fma.rn.f32x2 %0, %1, %2, %0;" : "+l"(d) : "l"(a), "l"(b));
}
__device__ __forceinline__ ull pk2(float a, float b) {
    ull r; asm("mov.b64 %0, {%1, %2};" : "=l"(r) : "f"(a), "f"(b)); return r;
}
__device__ __forceinline__ float2 up2(ull u) {
    float2 r; asm("mov.b64 {%0, %1}, %2;" : "=f"(r.x), "=f"(r.y) : "l"(u)); return r;
}

// ---------------- CSR build (A and B fused) ----------------
__global__ void zero2_kernel(int* degA, int* degB, int n) {
    int i = blockIdx.x * blockDim.x + threadIdx.x;
    if (i < n) degA[i] = 0;
    else if (i < 2 * n) degB[i - n] = 0;
}
__global__ void hist2_kernel(const int* __restrict__ dstA, const int* __restrict__ dstB,
                             int* degA, int* degB, int E) {
    int i = blockIdx.x * blockDim.x + threadIdx.x;
    if (i < E) atomicAdd(&degA[__ldg(&dstA[i])], 1);
    else if (i < 2 * E) atomicAdd(&degB[__ldg(&dstB[i - E])], 1);
}
// 2 blocks: block 0 scans degA -> rpA/cntA, block 1 scans degB -> rpB/cntB.
__global__ void scan2_kernel(const int* __restrict__ degA, const int* __restrict__ degB,
                             int* rpA, int* rpB, int* cntA, int* cntB, int n) {
    const int* deg = (blockIdx.x == 0) ? degA : degB;
    int* rp  = (blockIdx.x == 0) ? rpA : rpB;
    int* cnt = (blockIdx.x == 0) ? cntA : cntB;
    __shared__ int wsum[32];
    int tid = threadIdx.x, lane = tid & 31, wid = tid >> 5;
    int carry = 0;
    if (tid == 0) rp[0] = 0;
    for (int base = 0; base < n; base += 4096) {
        int i0 = base + tid * 4;
        int v[4];
#pragma unroll
        for (int k = 0; k < 4; k++) v[k] = (i0 + k < n) ? deg[i0 + k] : 0;
        int tsum = v[0] + v[1] + v[2] + v[3];
        int inc = tsum;
#pragma unroll
        for (int o = 1; o < 32; o <<= 1) {
            int t = __shfl_up_sync(0xffffffffu, inc, o);
            if (lane >= o) inc += t;
        }
        if (lane == 31) wsum[wid] = inc;
        __syncthreads();
        if (wid == 0) {
            int w = wsum[lane];
#pragma unroll
            for (int o = 1; o < 32; o <<= 1) {
                int t = __shfl_up_sync(0xffffffffu, w, o);
                if (lane >= o) w += t;
            }
            wsum[lane] = w;
        }
        __syncthreads();
        int woff = wid ? wsum[wid - 1] : 0;
        int excl = carry + woff + inc - tsum;
#pragma unroll
        for (int k = 0; k < 4; k++) {
            if (i0 + k < n) {
                cnt[i0 + k] = excl;
                excl += v[k];
                rp[i0 + k + 1] = excl;
            }
        }
        carry += wsum[31];
        __syncthreads();
    }
}
__global__ void scatter2_kernel(const int* __restrict__ eiA, const int* __restrict__ eiB,
                                int* cntA, int* cntB, int* colA, int* colB, int E) {
    int i = blockIdx.x * blockDim.x + threadIdx.x;
    if (i < E) {
        int p = atomicAdd(&cntA[__ldg(&eiA[E + i])], 1);
        colA[p] = __ldg(&eiA[i]);
    } else if (i < 2 * E) {
        int j = i - E;
        int p = atomicAdd(&cntB[__ldg(&eiB[E + j])], 1);
        colB[p] = __ldg(&eiB[j]);
    }
}

// ---------------- GEMM (128x128 tile, 8x8/thread, f32x2) + fused al/ar, fp16 H out ----------------
__global__ void __launch_bounds__(256, 2) gemm_fused_kernel(
    const float* __restrict__ X, const float* __restrict__ W,
    const float* __restrict__ a_s, const float* __restrict__ a_d,
    __half* __restrict__ H, float* __restrict__ al, float* __restrict__ ar, int nrows) {
    __shared__ float xs[32][132];                 // [k][row]
    __shared__ __align__(16) float ws[32][128];   // [k][col]
    int row0 = blockIdx.x * 128;
    int t = threadIdx.x;
    int tx = t & 15, ty = t >> 4;

    ull acc[8][4];
#pragma unroll
    for (int r = 0; r < 8; r++)
#pragma unroll
        for (int p = 0; p < 4; p++) acc[r][p] = 0ULL;

#pragma unroll 1
    for (int k0 = 0; k0 < DIM; k0 += 32) {
#pragma unroll
        for (int i = 0; i < 4; i++) {
            int slot = t + i * 256;
            int r = slot >> 3;
            int kq = (slot & 7) << 2;
            float4 v = make_float4(0.f, 0.f, 0.f, 0.f);
            if (row0 + r < nrows) v = *(const float4*)(X + (size_t)(row0 + r) * DIM + k0 + kq);
            xs[kq + 0][r] = v.x; xs[kq + 1][r] = v.y; xs[kq + 2][r] = v.z; xs[kq + 3][r] = v.w;
        }
#pragma unroll
        for (int i = 0; i < 4; i++) {
            int slot = t + i * 256;
            int kk = slot >> 5;
            int c4 = (slot & 31) << 2;
            *(float4*)(&ws[kk][c4]) = *(const float4*)(W + (size_t)(k0 + kk) * DIM + c4);
        }
        __syncthreads();
#pragma unroll
        for (int kk = 0; kk < 32; kk++) {
            float4 xa = *(const float4*)(&xs[kk][ty * 8]);
            float4 xb = *(const float4*)(&xs[kk][ty * 8 + 4]);
            ulonglong2 wA = *(const ulonglong2*)(&ws[kk][tx * 8]);
            ulonglong2 wB = *(const ulonglong2*)(&ws[kk][tx * 8 + 4]);
            ull xd;
            xd = pk2(xa.x, xa.x);
            fma2(acc[0][0], xd, wA.x); fma2(acc[0][1], xd, wA.y);
            fma2(acc[0][2], xd, wB.x); fma2(acc[0][3], xd, wB.y);
            xd = pk2(xa.y, xa.y);
            fma2(acc[1][0], xd, wA.x); fma2(acc[1][1], xd, wA.y);
            fma2(acc[1][2], xd, wB.x); fma2(acc[1][3], xd, wB.y);
            xd = pk2(xa.z, xa.z);
            fma2(acc[2][0], xd, wA.x); fma2(acc[2][1], xd, wA.y);
            fma2(acc[2][2], xd, wB.x); fma2(acc[2][3], xd, wB.y);
            xd = pk2(xa.w, xa.w);
            fma2(acc[3][0], xd, wA.x); fma2(acc[3][1], xd, wA.y);
            fma2(acc[3][2], xd, wB.x); fma2(acc[3][3], xd, wB.y);
            xd = pk2(xb.x, xb.x);
            fma2(acc[4][0], xd, wA.x); fma2(acc[4][1], xd, wA.y);
            fma2(acc[4][2], xd, wB.x); fma2(acc[4][3], xd, wB.y);
            xd = pk2(xb.y, xb.y);
            fma2(acc[5][0], xd, wA.x); fma2(acc[5][1], xd, wA.y);
            fma2(acc[5][2], xd, wB.x); fma2(acc[5][3], xd, wB.y);
            xd = pk2(xb.z, xb.z);
            fma2(acc[6][0], xd, wA.x); fma2(acc[6][1], xd, wA.y);
            fma2(acc[6][2], xd, wB.x); fma2(acc[6][3], xd, wB.y);
            xd = pk2(xb.w, xb.w);
            fma2(acc[7][0], xd, wA.x); fma2(acc[7][1], xd, wA.y);
            fma2(acc[7][2], xd, wB.x); fma2(acc[7][3], xd, wB.y);
        }
        __syncthreads();
    }

    // epilogue: fp16 H store + al/ar reduction (from exact fp32 acc)
    float as8[8], ad8[8];
#pragma unroll
    for (int c = 0; c < 8; c++) {
        as8[c] = __ldg(a_s + tx * 8 + c);
        ad8[c] = __ldg(a_d + tx * 8 + c);
    }
#pragma unroll
    for (int r = 0; r < 8; r++) {
        int row = row0 + ty * 8 + r;
        float2 p0 = up2(acc[r][0]), p1 = up2(acc[r][1]);
        float2 p2 = up2(acc[r][2]), p3 = up2(acc[r][3]);
        if (row < nrows) {
            __half2 q0 = __float22half2_rn(p0);
            __half2 q1 = __float22half2_rn(p1);
            __half2 q2 = __float22half2_rn(p2);
            __half2 q3 = __float22half2_rn(p3);
            uint4 st;
            st.x = *(unsigned*)&q0; st.y = *(unsigned*)&q1;
            st.z = *(unsigned*)&q2; st.w = *(unsigned*)&q3;
            ((uint4*)H)[(size_t)row * 16 + tx] = st;
        }
        float hv[8] = { p0.x, p0.y, p1.x, p1.y, p2.x, p2.y, p3.x, p3.y };
        float pal = 0.f, par = 0.f;
#pragma unroll
        for (int c = 0; c < 8; c++) {
            pal += hv[c] * as8[c];
            par += hv[c] * ad8[c];
        }
#pragma unroll
        for (int o = 8; o; o >>= 1) {
            pal += __shfl_xor_sync(0xffffffffu, pal, o);
            par += __shfl_xor_sync(0xffffffffu, par, o);
        }
        if (tx == 0 && row < nrows) {
            al[row] = pal;
            ar[row] = par;
        }
    }
}

// ---------------- GAT aggregation: warp per dst node, online softmax, fp16 gathers ----------------
__global__ void __launch_bounds__(256) aggregate_kernel(
    const __half* __restrict__ H, const float* __restrict__ al, const float* __restrict__ ar,
    const int* __restrict__ rowptr, const int* __restrict__ col,
    const float* __restrict__ bias, float* __restrict__ out, int n, int do_relu) {
    int w = (blockIdx.x * blockDim.x + threadIdx.x) >> 5;
    int lane = threadIdx.x & 31;
    if (w >= n) return;
    int start = rowptr[w];
    int end = rowptr[w + 1];
    float ard = ar[w];
    float m = lrelu(al[w] + ard);          // self-loop energy; running max

    const uint2* H2 = (const uint2*)H;      // 4 halves (cols lane*4..+3) per uint2
    uint2 sv = H2[(size_t)w * 32 + lane];
    float2 s0 = __half22float2(*(__half2*)&sv.x);
    float2 s1 = __half22float2(*(__half2*)&sv.y);
    float4 acc = make_float4(s0.x, s0.y, s1.x, s1.y);   // self weight exp(0)=1
    float ssum = (lane == 0) ? 1.f : 0.f;

    for (int base = start; base < end; base += 32) {
        int j = base + lane;
        int sj = 0;
        float ej = -1e30f;
        if (j < end) {
            sj = __ldg(&col[j]);
            ej = lrelu(__ldg(&al[sj]) + ard);
        }
        float bm = ej;
#pragma unroll
        for (int o = 16; o; o >>= 1) bm = fmaxf(bm, __shfl_xor_sync(0xffffffffu, bm, o));
        if (bm > m) {
            float sc = __expf(m - bm);
            m = bm;
            acc.x *= sc; acc.y *= sc; acc.z *= sc; acc.w *= sc;
            ssum *= sc;
        }
        float wj = (j < end) ? __expf(ej - m) : 0.f;
        ssum += wj;
        int cnt = min(32, end - base);
#pragma unroll 4
        for (int tt = 0; tt < cnt; tt++) {
            int s = __shfl_sync(0xffffffffu, sj, tt);
            float wt = __shfl_sync(0xffffffffu, wj, tt);
            uint2 v = H2[(size_t)s * 32 + lane];
            float2 f0 = __half22float2(*(__half2*)&v.x);
            float2 f1 = __half22float2(*(__half2*)&v.y);
            acc.x += wt * f0.x; acc.y += wt * f0.y;
            acc.z += wt * f1.x; acc.w += wt * f1.y;
        }
    }
#pragma unroll
    for (int o = 16; o; o >>= 1) ssum += __shfl_xor_sync(0xffffffffu, ssum, o);
    float inv = 1.0f / ssum;
    float4 bv = ((const float4*)bias)[lane];
    float4 o;
    o.x = acc.x * inv + bv.x; o.y = acc.y * inv + bv.y;
    o.z = acc.z * inv + bv.z; o.w = acc.w * inv + bv.w;
    if (do_relu) {
        o.x = fmaxf(o.x, 0.f); o.y = fmaxf(o.y, 0.f);
        o.z = fmaxf(o.z, 0.f); o.w = fmaxf(o.w, 0.f);
    }
    ((float4*)out)[(size_t)w * 32 + lane] = o;
}

// ---------------- launch ----------------
extern "C" void kernel_launch(void* const* d_in, const int* in_sizes, int n_in,
                              void* d_out, int out_size) {
    const float* x = (const float*)d_in[0];
    const float* W[5]; const float* As[5]; const float* Ad[5]; const float* B[5];
    for (int i = 0; i < 5; i++) {
        W[i]  = (const float*)d_in[1 + 4 * i];
        As[i] = (const float*)d_in[2 + 4 * i];
        Ad[i] = (const float*)d_in[3 + 4 * i];
        B[i]  = (const float*)d_in[4 + 4 * i];
    }
    const int* ei  = (const int*)d_in[21];
    const int* eic = (const int*)d_in[22];
    float* out = (float*)d_out;

    __half* h;
    float *bufA, *bufB, *al, *ar;
    int *rpA, *rpB, *colA, *colB, *degA, *degB, *cntA, *cntB;
    cudaGetSymbolAddress((void**)&h, g_h);
    cudaGetSymbolAddress((void**)&bufA, g_bufA);
    cudaGetSymbolAddress((void**)&bufB, g_bufB);
    cudaGetSymbolAddress((void**)&al, g_al);
    cudaGetSymbolAddress((void**)&ar, g_ar);
    cudaGetSymbolAddress((void**)&rpA, g_rpA);
    cudaGetSymbolAddress((void**)&rpB, g_rpB);
    cudaGetSymbolAddress((void**)&colA, g_colA);
    cudaGetSymbolAddress((void**)&colB, g_colB);
    cudaGetSymbolAddress((void**)&degA, g_degA);
    cudaGetSymbolAddress((void**)&degB, g_degB);
    cudaGetSymbolAddress((void**)&cntA, g_cntA);
    cudaGetSymbolAddress((void**)&cntB, g_cntB);

    const int N = NN, E = EE;
    int Gz2 = (2 * N + 255) / 256;
    int Ge2 = (2 * E + 255) / 256;
    int Gagg = (N * 32 + 255) / 256;
    int Gg = (N + 127) / 128;

    // CSR build: 4 launches total
    zero2_kernel<<<Gz2, 256>>>(degA, degB, N);
    hist2_kernel<<<Ge2, 256>>>(ei + E, eic + E, degA, degB, E);
    scan2_kernel<<<2, 1024>>>(degA, degB, rpA, rpB, cntA, cntB, N);
    scatter2_kernel<<<Ge2, 256>>>(ei, eic, cntA, cntB, colA, colB, E);

    const float* xin[5] = { x, bufA, bufB, bufA, bufB };
    float* xout[5]      = { bufA, bufB, bufA, bufB, out };
    const int* rp[5]    = { rpA, rpB, rpA, rpB, rpA };
    const int* cl[5]    = { colA, colB, colA, colB, colA };

    for (int i = 0; i < 5; i++) {
        gemm_fused_kernel<<<Gg, 256>>>(xin[i], W[i], As[i], Ad[i], h, al, ar, N);
        aggregate_kernel<<<Gagg, 256>>>(h, al, ar, rp[i], cl[i], B[i], xout[i], N,
                                        i < 4 ? 1 : 0);
    }
}